// round 16
// baseline (speedup 1.0000x reference)
#include <cuda_runtime.h>
#include <cuda_fp16.h>
#include <cstdint>

// GPTQ 4-bit linear, v16: single launch. Phase 1: all 148 CTAs convert
// x -> fp16 and W = fp16(s*(q-z)) into pre-tiled SW128 scratch (grid-stride).
// Grid barrier (sense reversal; all CTAs resident). Phase 2: v15 persistent
// GEMM (8 warps, 64x64 warp tile, continuous 4-stage TMA pipeline), with
// B-fragments loaded first and each A-ldsm interleaved with its MMA batch.

#define KDIM 4096
#define NDIM 4096
#define MMAX 8192
#define BM 256
#define BN 128
#define BK 64
#define STAGES 4
#define NTHREADS 256
#define KTILES (KDIM / BK)              // 64
#define TILES_X (NDIM / BN)             // 32
#define TILES_Y (MMAX / BM)             // 32
#define NTILES_TOTAL (TILES_X * TILES_Y)  // 1024
#define A_TILE_BYTES (BM * BK * 2)      // 32768
#define B_TILE_BYTES (BN * BK * 2)      // 16384
#define STAGE_BYTES (A_TILE_BYTES + B_TILE_BYTES)     // 49152
#define SMEM_HDR 1024
#define SMEM_TOTAL (SMEM_HDR + STAGES * STAGE_BYTES)  // 197632

#define XU ((size_t)MMAX * KDIM / 8)    // 4194304 x-conversion units (8 elems)
#define WU ((size_t)(KDIM / 8) * NDIM)  // 2097152 w-conversion units (1 word)

__device__ __align__(1024) __half g_xh[(size_t)MMAX * KDIM];
__device__ __align__(1024) __half g_wf[(size_t)NDIM * KDIM];
__device__ unsigned g_bar_count = 0;
__device__ unsigned g_bar_sense = 0;

__device__ __forceinline__ uint32_t swz128(uint32_t off) {
    return off ^ ((off >> 3) & 0x70);
}
__device__ __forceinline__ uint32_t smem_u32(const void* p) {
    uint32_t a;
    asm("{ .reg .u64 t; cvta.to.shared.u64 t, %1; cvt.u32.u64 %0, t; }" : "=r"(a) : "l"(p));
    return a;
}
__device__ __forceinline__ void mbar_init(uint32_t mbar, uint32_t count) {
    asm volatile("mbarrier.init.shared.b64 [%0], %1;" :: "r"(mbar), "r"(count) : "memory");
}
__device__ __forceinline__ void mbar_expect_tx(uint32_t mbar, uint32_t bytes) {
    asm volatile("mbarrier.arrive.expect_tx.shared.b64 _, [%0], %1;" :: "r"(mbar), "r"(bytes) : "memory");
}
__device__ __forceinline__ void mbar_arrive(uint32_t mbar) {
    asm volatile("mbarrier.arrive.shared.b64 _, [%0];" :: "r"(mbar) : "memory");
}
__device__ __forceinline__ void mbar_wait(uint32_t mbar, uint32_t parity) {
    asm volatile(
        "{\n\t.reg .pred P;\n\t"
        "WAIT_%=:\n\t"
        "mbarrier.try_wait.parity.acquire.cta.shared::cta.b64 P, [%0], %1, 0x989680;\n\t"
        "@!P bra WAIT_%=;\n\t}"
        :: "r"(mbar), "r"(parity) : "memory");
}
__device__ __forceinline__ void bulk_g2s(uint32_t dst, const void* src, uint32_t bytes, uint32_t mbar) {
    asm volatile(
        "cp.async.bulk.shared::cluster.global.mbarrier::complete_tx::bytes [%0], [%1], %2, [%3];"
        :: "r"(dst), "l"(src), "r"(bytes), "r"(mbar) : "memory");
}
__device__ __forceinline__ void ldsm_x4(uint32_t* r, uint32_t addr) {
    asm volatile("ldmatrix.sync.aligned.m8n8.x4.shared.b16 {%0,%1,%2,%3}, [%4];"
                 : "=r"(r[0]), "=r"(r[1]), "=r"(r[2]), "=r"(r[3]) : "r"(addr));
}
__device__ __forceinline__ void mma_16816(float* c, const uint32_t* a, uint32_t b0, uint32_t b1) {
    asm volatile(
        "mma.sync.aligned.m16n8k16.row.col.f32.f16.f16.f32 "
        "{%0,%1,%2,%3}, {%4,%5,%6,%7}, {%8,%9}, {%0,%1,%2,%3};"
        : "+f"(c[0]), "+f"(c[1]), "+f"(c[2]), "+f"(c[3])
        : "r"(a[0]), "r"(a[1]), "r"(a[2]), "r"(a[3]), "r"(b0), "r"(b1));
}

// tile index helpers: flat tile t -> scratch bases
__device__ __forceinline__ size_t a_base_of(int t) {
    return (size_t)(t >> 5) * (KTILES * A_TILE_BYTES);
}
__device__ __forceinline__ size_t b_base_of(int t) {
    return (size_t)(t & 31) * (KTILES * B_TILE_BYTES);
}

// ---------------------------------------------------------------------------
// Fused kernel: prep phase + grid barrier + persistent GEMM
// ---------------------------------------------------------------------------
__global__ __launch_bounds__(NTHREADS, 1)
void gemm_fused(const float* __restrict__ x,
                const int* __restrict__ qw, const int* __restrict__ qz,
                const float* __restrict__ sc,
                const float* __restrict__ bias, float* __restrict__ out) {
    extern __shared__ char smem[];
    const uint32_t sb = smem_u32(smem);
    const int tid = threadIdx.x;
    const int bid = blockIdx.x;
    const int gsz = gridDim.x;

    // ---------------- phase 1: prep (grid-stride) ----------------
    {
        const size_t stride = (size_t)gsz * NTHREADS;
        for (size_t u = (size_t)bid * NTHREADS + tid; u < XU + WU; u += stride) {
            if (u < XU) {
                int m  = (int)(u >> 9);
                int k0 = ((int)u & 511) << 3;
                const float* src = x + (size_t)m * KDIM + k0;
                float4 v0 = *reinterpret_cast<const float4*>(src);
                float4 v1 = *reinterpret_cast<const float4*>(src + 4);
                union { __half h[8]; uint4 q; } d;
                d.h[0] = __float2half_rn(v0.x); d.h[1] = __float2half_rn(v0.y);
                d.h[2] = __float2half_rn(v0.z); d.h[3] = __float2half_rn(v0.w);
                d.h[4] = __float2half_rn(v1.x); d.h[5] = __float2half_rn(v1.y);
                d.h[6] = __float2half_rn(v1.z); d.h[7] = __float2half_rn(v1.w);
                size_t off = ((size_t)(m >> 8) * KTILES + (k0 >> 6)) * A_TILE_BYTES
                           + swz128((uint32_t)((m & 255) * 128 + (k0 & 63) * 2));
                *reinterpret_cast<uint4*>(reinterpret_cast<char*>(g_xh) + off) = d.q;
            } else {
                int idx = (int)(u - XU);
                int kw = idx >> 12;                 // k/8: 0..511
                int n  = idx & 4095;
                int g  = kw >> 4;                   // k/128
                float s = sc[g * NDIM + n];
                int z = ((qz[g * (NDIM / 8) + (n >> 3)] >> ((n & 7) * 4)) & 15) + 1;
                int w = qw[kw * NDIM + n];
                union { __half h[8]; uint4 q; } d;
                #pragma unroll
                for (int j = 0; j < 8; j++) {
                    int qn = (w >> (j * 4)) & 15;
                    d.h[j] = __float2half_rn(s * (float)(qn - z));
                }
                int k0 = kw << 3;
                size_t off = ((size_t)(n >> 7) * KTILES + (k0 >> 6)) * B_TILE_BYTES
                           + swz128((uint32_t)((n & 127) * 128 + (k0 & 63) * 2));
                *reinterpret_cast<uint4*>(reinterpret_cast<char*>(g_wf) + off) = d.q;
            }
        }
    }

    // ---------------- grid barrier (sense reversal; all CTAs resident) -----
    __syncthreads();
    if (tid == 0) {
        __threadfence();
        unsigned sense0 = atomicAdd(&g_bar_sense, 0u);
        unsigned old = atomicAdd(&g_bar_count, 1u);
        if (old == (unsigned)gsz - 1u) {
            atomicExch(&g_bar_count, 0u);
            atomicAdd(&g_bar_sense, 1u);
        } else {
            while (atomicAdd(&g_bar_sense, 0u) == sense0) { }
        }
    }
    __syncthreads();

    // ---------------- phase 2: persistent GEMM ----------------
    const uint32_t mbar0 = sb;   // full[s]=sb+s*16, empty[s]=sb+s*16+8

    if (tid == 0) {
        #pragma unroll
        for (int s = 0; s < STAGES; s++) {
            mbar_init(mbar0 + s * 16, 1);       // full: tx-based
            mbar_init(mbar0 + s * 16 + 8, 8);   // empty: one arrive per warp
        }
    }
    __syncthreads();

    if (bid >= NTILES_TOTAL) return;
    const int ntiles = (NTILES_TOTAL - 1 - bid) / gsz + 1;
    const int G = ntiles << 6;

    if (tid == 0) {
        const size_t a0 = a_base_of(bid);
        const size_t b0 = b_base_of(bid);
        #pragma unroll
        for (int s = 0; s < STAGES; s++) {
            uint32_t full = mbar0 + s * 16;
            uint32_t st_s = sb + SMEM_HDR + s * STAGE_BYTES;
            mbar_expect_tx(full, STAGE_BYTES);
            bulk_g2s(st_s, (const char*)g_xh + a0 + (size_t)s * A_TILE_BYTES,
                     A_TILE_BYTES, full);
            bulk_g2s(st_s + A_TILE_BYTES,
                     (const char*)g_wf + b0 + (size_t)s * B_TILE_BYTES,
                     B_TILE_BYTES, full);
        }
    }

    const int warp = tid >> 5, lane = tid & 31;
    const int m0 = (warp >> 1) * 64;            // 4 warps in M, 64 rows each
    const int n0 = (warp & 1) * 64;             // 2 warps in N, 64 cols each
    const int t4 = lane & 3;
    const int laneA_r  = lane & 15;
    const int laneA_kc = (lane >> 4) & 1;
    const int laneB_r  = (lane & 7) | ((lane >> 4) << 3);
    const int laneB_kc = (lane >> 3) & 1;
    const int g4 = lane >> 2;

    float acc[4][8][4];
    #pragma unroll
    for (int i = 0; i < 4; i++)
        #pragma unroll
        for (int j = 0; j < 8; j++)
            #pragma unroll
            for (int c = 0; c < 4; c++) acc[i][j][c] = 0.0f;

    for (int g = 0; g < G; g++) {
        const int st = g & (STAGES - 1);
        const uint32_t ph = (uint32_t)(g >> 2) & 1u;
        const uint32_t full  = mbar0 + st * 16;
        const uint32_t empty = full + 8;
        const uint32_t a_s = sb + SMEM_HDR + st * STAGE_BYTES;
        const uint32_t b_s = a_s + A_TILE_BYTES;

        mbar_wait(full, ph);

        #pragma unroll
        for (int ks = 0; ks < 4; ks++) {
            // B fragments first
            uint32_t b[8][2];
            #pragma unroll
            for (int bi = 0; bi < 4; bi++) {
                uint32_t r[4];
                uint32_t byte = (uint32_t)((n0 + bi * 16 + laneB_r) * 128
                                           + ks * 32 + laneB_kc * 16);
                ldsm_x4(r, b_s + swz128(byte));
                b[2 * bi][0] = r[0]; b[2 * bi][1] = r[1];
                b[2 * bi + 1][0] = r[2]; b[2 * bi + 1][1] = r[3];
            }
            // interleave: each A-ldsm immediately followed by its 8 MMAs
            #pragma unroll
            for (int mi = 0; mi < 4; mi++) {
                uint32_t a[4];
                uint32_t byte = (uint32_t)((m0 + mi * 16 + laneA_r) * 128
                                           + ks * 32 + laneA_kc * 16);
                ldsm_x4(a, a_s + swz128(byte));
                // free the stage right after the very last smem read of this tile
                if (ks == 3 && mi == 3 && lane == 0) mbar_arrive(empty);
                #pragma unroll
                for (int ni = 0; ni < 8; ni++)
                    mma_16816(acc[mi][ni], a, b[ni][0], b[ni][1]);
            }
        }

        // producer: refill stage st for global iteration g+STAGES (crosses tiles)
        if (tid == 0) {
            const int pre = g + STAGES;
            if (pre < G) {
                const int pt = bid + (pre >> 6) * gsz;
                const int pit = pre & 63;
                mbar_wait(empty, ph);
                mbar_expect_tx(full, STAGE_BYTES);
                bulk_g2s(a_s, (const char*)g_xh + a_base_of(pt)
                              + (size_t)pit * A_TILE_BYTES, A_TILE_BYTES, full);
                bulk_g2s(b_s, (const char*)g_wf + b_base_of(pt)
                              + (size_t)pit * B_TILE_BYTES, B_TILE_BYTES, full);
            }
        }

        // tile boundary: epilogue + accumulator reset (pipeline keeps running)
        if ((g & 63) == 63) {
            const int t = bid + (g >> 6) * gsz;
            const int bm = (t >> 5) * BM;
            const int bn = (t & 31) * BN;
            #pragma unroll
            for (int mi = 0; mi < 4; mi++) {
                const int row0 = bm + m0 + mi * 16 + g4;
                #pragma unroll
                for (int ni = 0; ni < 8; ni++) {
                    const int col = bn + n0 + ni * 8 + t4 * 2;
                    const float2 bz = *reinterpret_cast<const float2*>(&bias[col]);
                    float2 v0, v1;
                    v0.x = acc[mi][ni][0] + bz.x;
                    v0.y = acc[mi][ni][1] + bz.y;
                    v1.x = acc[mi][ni][2] + bz.x;
                    v1.y = acc[mi][ni][3] + bz.y;
                    *reinterpret_cast<float2*>(&out[(size_t)row0 * NDIM + col]) = v0;
                    *reinterpret_cast<float2*>(&out[(size_t)(row0 + 8) * NDIM + col]) = v1;
                    acc[mi][ni][0] = 0.0f; acc[mi][ni][1] = 0.0f;
                    acc[mi][ni][2] = 0.0f; acc[mi][ni][3] = 0.0f;
                }
            }
        }
    }
}

// ---------------------------------------------------------------------------
extern "C" void kernel_launch(void* const* d_in, const int* in_sizes, int n_in,
                              void* d_out, int out_size)
{
    const float* x    = (const float*)d_in[0];
    const int*   qw   = (const int*)  d_in[1];
    const int*   qz   = (const int*)  d_in[2];
    const float* sc   = (const float*)d_in[3];
    const float* bias = (const float*)d_in[4];
    float*       out  = (float*)d_out;

    int nsm = 148;
    cudaDeviceGetAttribute(&nsm, cudaDevAttrMultiProcessorCount, 0);
    if (nsm <= 0 || nsm > NTILES_TOTAL) nsm = 148;

    cudaFuncSetAttribute(gemm_fused, cudaFuncAttributeMaxDynamicSharedMemorySize, SMEM_TOTAL);
    gemm_fused<<<nsm, NTHREADS, SMEM_TOTAL>>>(x, qw, qz, sc, bias, out);
}

// round 17
// speedup vs baseline: 1.1149x; 1.1149x over previous
#include <cuda_runtime.h>
#include <cuda_fp16.h>
#include <cstdint>

// GPTQ 4-bit linear, v17: v15 persistent GEMM (best 614.4us) with ONE change:
// B-first interleaved k-step (B fragments loaded first, each A-ldsm followed
// immediately by its 8 MMAs). Prep back to the proven separate 24576-block
// kernel (roofline ~36us).

#define KDIM 4096
#define NDIM 4096
#define MMAX 8192
#define BM 256
#define BN 128
#define BK 64
#define STAGES 4
#define NTHREADS 256
#define KTILES (KDIM / BK)              // 64
#define TILES_X (NDIM / BN)             // 32
#define TILES_Y (MMAX / BM)             // 32
#define NTILES_TOTAL (TILES_X * TILES_Y)  // 1024
#define A_TILE_BYTES (BM * BK * 2)      // 32768
#define B_TILE_BYTES (BN * BK * 2)      // 16384
#define STAGE_BYTES (A_TILE_BYTES + B_TILE_BYTES)     // 49152
#define SMEM_HDR 1024
#define SMEM_TOTAL (SMEM_HDR + STAGES * STAGE_BYTES)  // 197632

#define XBLKS 16384
#define WBLKS 8192

__device__ __align__(1024) __half g_xh[(size_t)MMAX * KDIM];
__device__ __align__(1024) __half g_wf[(size_t)NDIM * KDIM];

__device__ __forceinline__ uint32_t swz128(uint32_t off) {
    return off ^ ((off >> 3) & 0x70);
}
__device__ __forceinline__ uint32_t smem_u32(const void* p) {
    uint32_t a;
    asm("{ .reg .u64 t; cvta.to.shared.u64 t, %1; cvt.u32.u64 %0, t; }" : "=r"(a) : "l"(p));
    return a;
}
__device__ __forceinline__ void mbar_init(uint32_t mbar, uint32_t count) {
    asm volatile("mbarrier.init.shared.b64 [%0], %1;" :: "r"(mbar), "r"(count) : "memory");
}
__device__ __forceinline__ void mbar_expect_tx(uint32_t mbar, uint32_t bytes) {
    asm volatile("mbarrier.arrive.expect_tx.shared.b64 _, [%0], %1;" :: "r"(mbar), "r"(bytes) : "memory");
}
__device__ __forceinline__ void mbar_arrive(uint32_t mbar) {
    asm volatile("mbarrier.arrive.shared.b64 _, [%0];" :: "r"(mbar) : "memory");
}
__device__ __forceinline__ void mbar_wait(uint32_t mbar, uint32_t parity) {
    asm volatile(
        "{\n\t.reg .pred P;\n\t"
        "WAIT_%=:\n\t"
        "mbarrier.try_wait.parity.acquire.cta.shared::cta.b64 P, [%0], %1, 0x989680;\n\t"
        "@!P bra WAIT_%=;\n\t}"
        :: "r"(mbar), "r"(parity) : "memory");
}
__device__ __forceinline__ void bulk_g2s(uint32_t dst, const void* src, uint32_t bytes, uint32_t mbar) {
    asm volatile(
        "cp.async.bulk.shared::cluster.global.mbarrier::complete_tx::bytes [%0], [%1], %2, [%3];"
        :: "r"(dst), "l"(src), "r"(bytes), "r"(mbar) : "memory");
}
__device__ __forceinline__ void ldsm_x4(uint32_t* r, uint32_t addr) {
    asm volatile("ldmatrix.sync.aligned.m8n8.x4.shared.b16 {%0,%1,%2,%3}, [%4];"
                 : "=r"(r[0]), "=r"(r[1]), "=r"(r[2]), "=r"(r[3]) : "r"(addr));
}
__device__ __forceinline__ void mma_16816(float* c, const uint32_t* a, uint32_t b0, uint32_t b1) {
    asm volatile(
        "mma.sync.aligned.m16n8k16.row.col.f32.f16.f16.f32 "
        "{%0,%1,%2,%3}, {%4,%5,%6,%7}, {%8,%9}, {%0,%1,%2,%3};"
        : "+f"(c[0]), "+f"(c[1]), "+f"(c[2]), "+f"(c[3])
        : "r"(a[0]), "r"(a[1]), "r"(a[2]), "r"(a[3]), "r"(b0), "r"(b1));
}

// ---------------------------------------------------------------------------
// Fused prep (separate launch, 24576 blocks): x -> fp16 tiles; W -> fp16 tiles.
// ---------------------------------------------------------------------------
__global__ void prep(const float* __restrict__ x,
                     const int* __restrict__ qw, const int* __restrict__ qz,
                     const float* __restrict__ sc) {
    if (blockIdx.x < XBLKS) {
        size_t idx = (size_t)blockIdx.x * blockDim.x + threadIdx.x;  // per 8 elems
        int m  = (int)(idx >> 9);
        int k0 = ((int)idx & 511) << 3;

        const float* src = x + (size_t)m * KDIM + k0;
        float4 v0 = *reinterpret_cast<const float4*>(src);
        float4 v1 = *reinterpret_cast<const float4*>(src + 4);

        union { __half h[8]; uint4 u; } d;
        d.h[0] = __float2half_rn(v0.x); d.h[1] = __float2half_rn(v0.y);
        d.h[2] = __float2half_rn(v0.z); d.h[3] = __float2half_rn(v0.w);
        d.h[4] = __float2half_rn(v1.x); d.h[5] = __float2half_rn(v1.y);
        d.h[6] = __float2half_rn(v1.z); d.h[7] = __float2half_rn(v1.w);

        size_t off = ((size_t)(m >> 8) * KTILES + (k0 >> 6)) * A_TILE_BYTES
                   + swz128((uint32_t)((m & 255) * 128 + (k0 & 63) * 2));
        *reinterpret_cast<uint4*>(reinterpret_cast<char*>(g_xh) + off) = d.u;
    } else {
        int idx = (blockIdx.x - XBLKS) * blockDim.x + threadIdx.x;  // per qw word
        int kw = idx >> 12;                 // k/8: 0..511
        int n  = idx & 4095;
        int g  = kw >> 4;                   // k/128
        float s = sc[g * NDIM + n];
        int z = ((qz[g * (NDIM / 8) + (n >> 3)] >> ((n & 7) * 4)) & 15) + 1;
        int w = qw[kw * NDIM + n];

        union { __half h[8]; uint4 u; } d;
        #pragma unroll
        for (int j = 0; j < 8; j++) {
            int q = (w >> (j * 4)) & 15;
            d.h[j] = __float2half_rn(s * (float)(q - z));
        }

        int k0 = kw << 3;
        size_t off = ((size_t)(n >> 7) * KTILES + (k0 >> 6)) * B_TILE_BYTES
                   + swz128((uint32_t)((n & 127) * 128 + (k0 & 63) * 2));
        *reinterpret_cast<uint4*>(reinterpret_cast<char*>(g_wf) + off) = d.u;
    }
}

// tile index helpers
__device__ __forceinline__ size_t a_base_of(int t) {
    return (size_t)(t >> 5) * (KTILES * A_TILE_BYTES);
}
__device__ __forceinline__ size_t b_base_of(int t) {
    return (size_t)(t & 31) * (KTILES * B_TILE_BYTES);
}

// ---------------------------------------------------------------------------
// GEMM: persistent, 8 warps, warp tile 64x64, tid0 producer,
//       B-first interleaved k-step
// ---------------------------------------------------------------------------
__global__ __launch_bounds__(NTHREADS, 1)
void gemm_mma(const float* __restrict__ bias, float* __restrict__ out) {
    extern __shared__ char smem[];
    const uint32_t sb = smem_u32(smem);
    const int tid = threadIdx.x;
    const int bid = blockIdx.x;
    const int gsz = gridDim.x;

    const uint32_t mbar0 = sb;   // full[s]=sb+s*16, empty[s]=sb+s*16+8

    if (tid == 0) {
        #pragma unroll
        for (int s = 0; s < STAGES; s++) {
            mbar_init(mbar0 + s * 16, 1);       // full: tx-based
            mbar_init(mbar0 + s * 16 + 8, 8);   // empty: one arrive per warp
        }
    }
    __syncthreads();

    if (bid >= NTILES_TOTAL) return;
    const int ntiles = (NTILES_TOTAL - 1 - bid) / gsz + 1;
    const int G = ntiles << 6;

    if (tid == 0) {
        const size_t a0 = a_base_of(bid);
        const size_t b0 = b_base_of(bid);
        #pragma unroll
        for (int s = 0; s < STAGES; s++) {
            uint32_t full = mbar0 + s * 16;
            uint32_t st_s = sb + SMEM_HDR + s * STAGE_BYTES;
            mbar_expect_tx(full, STAGE_BYTES);
            bulk_g2s(st_s, (const char*)g_xh + a0 + (size_t)s * A_TILE_BYTES,
                     A_TILE_BYTES, full);
            bulk_g2s(st_s + A_TILE_BYTES,
                     (const char*)g_wf + b0 + (size_t)s * B_TILE_BYTES,
                     B_TILE_BYTES, full);
        }
    }

    const int warp = tid >> 5, lane = tid & 31;
    const int m0 = (warp >> 1) * 64;            // 4 warps in M, 64 rows each
    const int n0 = (warp & 1) * 64;             // 2 warps in N, 64 cols each
    const int t4 = lane & 3;
    const int laneA_r  = lane & 15;
    const int laneA_kc = (lane >> 4) & 1;
    const int laneB_r  = (lane & 7) | ((lane >> 4) << 3);
    const int laneB_kc = (lane >> 3) & 1;
    const int g4 = lane >> 2;

    float acc[4][8][4];
    #pragma unroll
    for (int i = 0; i < 4; i++)
        #pragma unroll
        for (int j = 0; j < 8; j++)
            #pragma unroll
            for (int c = 0; c < 4; c++) acc[i][j][c] = 0.0f;

    for (int g = 0; g < G; g++) {
        const int st = g & (STAGES - 1);
        const uint32_t ph = (uint32_t)(g >> 2) & 1u;
        const uint32_t full  = mbar0 + st * 16;
        const uint32_t empty = full + 8;
        const uint32_t a_s = sb + SMEM_HDR + st * STAGE_BYTES;
        const uint32_t b_s = a_s + A_TILE_BYTES;

        mbar_wait(full, ph);

        #pragma unroll
        for (int ks = 0; ks < 4; ks++) {
            // B fragments first
            uint32_t b[8][2];
            #pragma unroll
            for (int bi = 0; bi < 4; bi++) {
                uint32_t r[4];
                uint32_t byte = (uint32_t)((n0 + bi * 16 + laneB_r) * 128
                                           + ks * 32 + laneB_kc * 16);
                ldsm_x4(r, b_s + swz128(byte));
                b[2 * bi][0] = r[0]; b[2 * bi][1] = r[1];
                b[2 * bi + 1][0] = r[2]; b[2 * bi + 1][1] = r[3];
            }
            // each A-ldsm immediately followed by its 8 MMAs
            #pragma unroll
            for (int mi = 0; mi < 4; mi++) {
                uint32_t a[4];
                uint32_t byte = (uint32_t)((m0 + mi * 16 + laneA_r) * 128
                                           + ks * 32 + laneA_kc * 16);
                ldsm_x4(a, a_s + swz128(byte));
                // free the stage right after the tile's very last smem read
                if (ks == 3 && mi == 3 && lane == 0) mbar_arrive(empty);
                #pragma unroll
                for (int ni = 0; ni < 8; ni++)
                    mma_16816(acc[mi][ni], a, b[ni][0], b[ni][1]);
            }
        }

        // producer: refill stage st for global iteration g+STAGES (crosses tiles)
        if (tid == 0) {
            const int pre = g + STAGES;
            if (pre < G) {
                const int pt = bid + (pre >> 6) * gsz;
                const int pit = pre & 63;
                mbar_wait(empty, ph);
                mbar_expect_tx(full, STAGE_BYTES);
                bulk_g2s(a_s, (const char*)g_xh + a_base_of(pt)
                              + (size_t)pit * A_TILE_BYTES, A_TILE_BYTES, full);
                bulk_g2s(b_s, (const char*)g_wf + b_base_of(pt)
                              + (size_t)pit * B_TILE_BYTES, B_TILE_BYTES, full);
            }
        }

        // tile boundary: epilogue + accumulator reset (pipeline keeps running)
        if ((g & 63) == 63) {
            const int t = bid + (g >> 6) * gsz;
            const int bm = (t >> 5) * BM;
            const int bn = (t & 31) * BN;
            #pragma unroll
            for (int mi = 0; mi < 4; mi++) {
                const int row0 = bm + m0 + mi * 16 + g4;
                #pragma unroll
                for (int ni = 0; ni < 8; ni++) {
                    const int col = bn + n0 + ni * 8 + t4 * 2;
                    const float2 bz = *reinterpret_cast<const float2*>(&bias[col]);
                    float2 v0, v1;
                    v0.x = acc[mi][ni][0] + bz.x;
                    v0.y = acc[mi][ni][1] + bz.y;
                    v1.x = acc[mi][ni][2] + bz.x;
                    v1.y = acc[mi][ni][3] + bz.y;
                    *reinterpret_cast<float2*>(&out[(size_t)row0 * NDIM + col]) = v0;
                    *reinterpret_cast<float2*>(&out[(size_t)(row0 + 8) * NDIM + col]) = v1;
                    acc[mi][ni][0] = 0.0f; acc[mi][ni][1] = 0.0f;
                    acc[mi][ni][2] = 0.0f; acc[mi][ni][3] = 0.0f;
                }
            }
        }
    }
}

// ---------------------------------------------------------------------------
extern "C" void kernel_launch(void* const* d_in, const int* in_sizes, int n_in,
                              void* d_out, int out_size)
{
    const float* x    = (const float*)d_in[0];
    const int*   qw   = (const int*)  d_in[1];
    const int*   qz   = (const int*)  d_in[2];
    const float* sc   = (const float*)d_in[3];
    const float* bias = (const float*)d_in[4];
    float*       out  = (float*)d_out;

    prep<<<XBLKS + WBLKS, 256>>>(x, qw, qz, sc);

    int nsm = 148;
    cudaDeviceGetAttribute(&nsm, cudaDevAttrMultiProcessorCount, 0);
    if (nsm <= 0 || nsm > NTILES_TOTAL) nsm = 148;

    cudaFuncSetAttribute(gemm_mma, cudaFuncAttributeMaxDynamicSharedMemorySize, SMEM_TOTAL);
    gemm_mma<<<nsm, NTHREADS, SMEM_TOTAL>>>(bias, out);
}